// round 1
// baseline (speedup 1.0000x reference)
#include <cuda_runtime.h>
#include <math.h>

#define Bb 16
#define Ss 8192
#define Hh 256

constexpr int CTX_ELEMS = Bb * Hh;      // 4096, context first in d_out
constexpr int ATT_OFF   = CTX_ELEMS;    // attn weights follow

// -------- scratch (__device__ globals: no allocation allowed) --------
__device__ float g_WkT[Hh * Hh];        // Wk transposed to [h][o] (k-major)
__device__ float g_qproj[Bb * Hh];      // q @ Wq^T + b_attn
__device__ float g_maxv[Bb];
__device__ float g_invsum[Bb];
__device__ float g_ctxpart[Bb * 16 * Hh];

// -------- f32x2 helpers (sm_103a packed fp32 pipe) --------
__device__ __forceinline__ unsigned long long pk2(float lo, float hi) {
    unsigned long long r;
    asm("mov.b64 %0, {%1, %2};" : "=l"(r) : "f"(lo), "f"(hi));
    return r;
}
__device__ __forceinline__ unsigned long long ffma2(unsigned long long a,
                                                    unsigned long long b,
                                                    unsigned long long c) {
    unsigned long long d;
    asm("fma.rn.f32x2 %0, %1, %2, %3;" : "=l"(d) : "l"(a), "l"(b), "l"(c));
    return d;
}
__device__ __forceinline__ void unpk2(unsigned long long x, float& lo, float& hi) {
    asm("mov.b64 {%0, %1}, %2;" : "=f"(lo), "=f"(hi) : "l"(x));
}

// ---------------- phase A0: transpose Wk ----------------
// g_WkT[h][o] = W_attn[o][Hh + h]
__global__ void k_transpose(const float* __restrict__ W) {
    int h = blockIdx.x;
    int o = threadIdx.x;
    g_WkT[h * Hh + o] = W[o * (2 * Hh) + Hh + h];
}

// ---------------- phase A1: q projection ----------------
// g_qproj[b][o] = sum_h q[b][h] * W_attn[o][h] + b_attn[o]
__global__ void k_qproj(const float* __restrict__ q, const float* __restrict__ W,
                        const float* __restrict__ bvec) {
    __shared__ float sq[Hh];
    int b = blockIdx.x, o = threadIdx.x;
    sq[o] = q[b * Hh + o];
    __syncthreads();
    float s = bvec[o];
    const float* row = W + o * (2 * Hh);
#pragma unroll 8
    for (int h = 0; h < Hh; ++h) s += sq[h] * row[h];
    g_qproj[b * Hh + o] = s;
}

// ---------------- phase B: key GEMM + tanh + dot(v) -> raw scores ----------------
#define BS   128           // s-rows per block
#define KC   16            // k-chunk
#define KPAD 20            // sK row stride (floats), multiple of 4, kills store conflicts
#define NTHR 512

__global__ __launch_bounds__(NTHR, 1)
void k_scores(const float* __restrict__ key, const float* __restrict__ vvec,
              float* __restrict__ out) {
    __shared__ float sK[BS * KPAD];     // 10 KB
    __shared__ float sW[KC * Hh];       // 16 KB

    const int tid = threadIdx.x;
    const int tc  = tid & 31;           // col-thread 0..31, lanes of one warp
    const int tr  = tid >> 5;           // row-thread 0..15 = warp id
    const int b   = blockIdx.x >> 6;    // 64 blocks per batch (8192/128)
    const int s0  = (blockIdx.x & 63) * BS;
    const float* kbase = key + ((long long)b * Ss + s0) * Hh;

    // acc[j][c]: 8 rows x 4 f32x2-pairs = 8x8 fp32 tile
    // rows: j<4 -> tr*4+j ; j>=4 -> 64+tr*4+(j-4)
    // cols: c=0 -> (tc*4+0, tc*4+1), c=1 -> (tc*4+2, +3), c=2/3 -> same +128
    unsigned long long acc[8][4];
#pragma unroll
    for (int j = 0; j < 8; ++j)
#pragma unroll
        for (int c = 0; c < 4; ++c) acc[j][c] = 0ull;

    // loader mapping
    const int lr  = tid >> 2;          // key row 0..127
    const int lc4 = tid & 3;           // key f4-col 0..3 (KC=16)
    const int wkk0 = tid >> 6, wo0 = tid & 63;           // W f4 idx tid
    const int wkk1 = (tid + 512) >> 6, wo1 = (tid + 512) & 63; // W f4 idx tid+512

    // prefetch chunk 0 into registers
    float4 pK  = *(const float4*)(kbase + lr * Hh + lc4 * 4);
    float4 pW0 = *(const float4*)(g_WkT + wkk0 * Hh + wo0 * 4);
    float4 pW1 = *(const float4*)(g_WkT + wkk1 * Hh + wo1 * 4);

    for (int ch = 0; ch < Hh / KC; ++ch) {
        *(float4*)(sK + lr * KPAD + lc4 * 4) = pK;
        *(float4*)(sW + wkk0 * Hh + wo0 * 4) = pW0;
        *(float4*)(sW + wkk1 * Hh + wo1 * 4) = pW1;
        __syncthreads();
        if (ch + 1 < Hh / KC) {
            int h0 = (ch + 1) * KC;
            pK  = *(const float4*)(kbase + lr * Hh + h0 + lc4 * 4);
            pW0 = *(const float4*)(g_WkT + (h0 + wkk0) * Hh + wo0 * 4);
            pW1 = *(const float4*)(g_WkT + (h0 + wkk1) * Hh + wo1 * 4);
        }
#pragma unroll
        for (int k = 0; k < KC; k += 2) {
            float2 kA[8];
#pragma unroll
            for (int j = 0; j < 8; ++j) {
                int row = (j < 4) ? (tr * 4 + j) : (64 + tr * 4 + (j - 4));
                kA[j] = *(const float2*)(sK + row * KPAD + k);
            }
#pragma unroll
            for (int u = 0; u < 2; ++u) {
                const float* wr = sW + (k + u) * Hh;
                float4 w0 = *(const float4*)(wr + tc * 4);
                float4 w1 = *(const float4*)(wr + 128 + tc * 4);
                unsigned long long wp0 = pk2(w0.x, w0.y), wp1 = pk2(w0.z, w0.w);
                unsigned long long wp2 = pk2(w1.x, w1.y), wp3 = pk2(w1.z, w1.w);
#pragma unroll
                for (int j = 0; j < 8; ++j) {
                    float kv = u ? kA[j].y : kA[j].x;
                    unsigned long long kp = pk2(kv, kv);
                    acc[j][0] = ffma2(kp, wp0, acc[j][0]);
                    acc[j][1] = ffma2(kp, wp1, acc[j][1]);
                    acc[j][2] = ffma2(kp, wp2, acc[j][2]);
                    acc[j][3] = ffma2(kp, wp3, acc[j][3]);
                }
            }
        }
        __syncthreads();
    }

    // epilogue: hidden = tanh(acc + qproj), row score partial = dot(hidden, v)
    float qb[8], vv[8];
#pragma unroll
    for (int i = 0; i < 4; ++i) {
        qb[i]     = g_qproj[b * Hh + tc * 4 + i];
        qb[4 + i] = g_qproj[b * Hh + 128 + tc * 4 + i];
        vv[i]     = vvec[tc * 4 + i];
        vv[4 + i] = vvec[128 + tc * 4 + i];
    }
    float rs[8];
#pragma unroll
    for (int j = 0; j < 8; ++j) {
        float s = 0.f;
#pragma unroll
        for (int c = 0; c < 4; ++c) {
            float lo, hi;
            unpk2(acc[j][c], lo, hi);
            int ci = (c < 2) ? (2 * c) : (4 + 2 * (c - 2));
            s += tanhf(lo + qb[ci]) * vv[ci];
            s += tanhf(hi + qb[ci + 1]) * vv[ci + 1];
        }
        rs[j] = s;
    }
#pragma unroll
    for (int off = 16; off; off >>= 1) {
#pragma unroll
        for (int j = 0; j < 8; ++j)
            rs[j] += __shfl_xor_sync(0xffffffffu, rs[j], off);
    }
    if (tc == 0) {
        float* sc = out + ATT_OFF + b * Ss + s0;
#pragma unroll
        for (int j = 0; j < 4; ++j) sc[tr * 4 + j] = rs[j];
#pragma unroll
        for (int j = 0; j < 4; ++j) sc[64 + tr * 4 + j] = rs[4 + j];
    }
}

// ---------------- phase C: per-batch softmax stats ----------------
__global__ void k_softmax_stats(const float* __restrict__ out) {
    __shared__ float red[256];
    int b = blockIdx.x, t = threadIdx.x;
    const float* sc = out + ATT_OFF + b * Ss;
    float m = -1e30f;
    for (int i = t; i < Ss; i += 256) m = fmaxf(m, sc[i]);
    red[t] = m; __syncthreads();
    for (int st = 128; st; st >>= 1) {
        if (t < st) red[t] = fmaxf(red[t], red[t + st]);
        __syncthreads();
    }
    float mx = red[0]; __syncthreads();
    float s = 0.f;
    for (int i = t; i < Ss; i += 256) s += expf(sc[i] - mx);
    red[t] = s; __syncthreads();
    for (int st = 128; st; st >>= 1) {
        if (t < st) red[t] += red[t + st];
        __syncthreads();
    }
    if (t == 0) { g_maxv[b] = mx; g_invsum[b] = 1.f / red[0]; }
}

// ---------------- phase D: normalize weights + partial context ----------------
#define DCH 512
__global__ void k_context(const float* __restrict__ value, float* __restrict__ out) {
    __shared__ float sw[DCH];
    int b  = blockIdx.x >> 4;
    int ch = blockIdx.x & 15;
    int s0 = ch * DCH;
    int t  = threadIdx.x;   // 256
    float mx = g_maxv[b], is = g_invsum[b];
    float* att = out + ATT_OFF + b * Ss;
#pragma unroll
    for (int i = 0; i < 2; ++i) {
        int s = s0 + t + i * 256;
        float w = expf(att[s] - mx) * is;
        att[s] = w;
        sw[t + i * 256] = w;
    }
    __syncthreads();
    const float* vb = value + ((long long)b * Ss + s0) * Hh + t;
    float a0 = 0.f, a1 = 0.f, a2 = 0.f, a3 = 0.f;
#pragma unroll 2
    for (int s = 0; s < DCH; s += 4) {
        a0 += sw[s]     * __ldg(vb + (long long)(s)     * Hh);
        a1 += sw[s + 1] * __ldg(vb + (long long)(s + 1) * Hh);
        a2 += sw[s + 2] * __ldg(vb + (long long)(s + 2) * Hh);
        a3 += sw[s + 3] * __ldg(vb + (long long)(s + 3) * Hh);
    }
    g_ctxpart[(b * 16 + ch) * Hh + t] = (a0 + a1) + (a2 + a3);
}

// ---------------- phase E: reduce partial contexts ----------------
__global__ void k_reduce_ctx(float* __restrict__ out) {
    int b = blockIdx.x, t = threadIdx.x;
    float s = 0.f;
#pragma unroll
    for (int c = 0; c < 16; ++c) s += g_ctxpart[(b * 16 + c) * Hh + t];
    out[b * Hh + t] = s;
}

// ---------------- launch ----------------
extern "C" void kernel_launch(void* const* d_in, const int* in_sizes, int n_in,
                              void* d_out, int out_size) {
    const float* query  = (const float*)d_in[0];
    const float* key    = (const float*)d_in[1];
    const float* value  = (const float*)d_in[2];
    const float* W_attn = (const float*)d_in[3];
    const float* b_attn = (const float*)d_in[4];
    const float* v      = (const float*)d_in[5];
    float* out = (float*)d_out;

    k_transpose<<<Hh, Hh>>>(W_attn);
    k_qproj<<<Bb, Hh>>>(query, W_attn, b_attn);
    k_scores<<<(Bb * Ss) / BS, NTHR>>>(key, v, out);
    k_softmax_stats<<<Bb, 256>>>(out);
    k_context<<<Bb * 16, 256>>>(value, out);
    k_reduce_ctx<<<Bb, Hh>>>(out);
}

// round 3
// speedup vs baseline: 1.9696x; 1.9696x over previous
#include <cuda_runtime.h>
#include <cuda_fp16.h>
#include <math.h>
#include <cstdint>

#define Bb 16
#define Ss 8192
#define Hh 256

constexpr int CTX_ELEMS = Bb * Hh;
constexpr int ATT_OFF   = CTX_ELEMS;

// -------- scratch (__device__ globals: no allocation allowed) --------
__device__ float g_qproj[Bb * Hh];
__device__ float g_maxv[Bb];
__device__ float g_invsum[Bb];
__device__ float g_ctxpart[Bb * 16 * Hh];
__device__ __half g_Bh[Hh * Hh];   // Wk hi, [o][k] row-major
__device__ __half g_Bl[Hh * Hh];   // Wk lo

// ---------------- helpers ----------------
__device__ __forceinline__ uint32_t smem_u32(const void* p) {
    uint32_t a;
    asm("{ .reg .u64 t; cvta.to.shared.u64 t, %1; cvt.u32.u64 %0, t; }" : "=r"(a) : "l"(p));
    return a;
}
__device__ __forceinline__ void ldmx4(uint32_t& r0, uint32_t& r1, uint32_t& r2, uint32_t& r3,
                                      uint32_t addr) {
    asm volatile("ldmatrix.sync.aligned.m8n8.x4.shared.b16 {%0,%1,%2,%3}, [%4];"
                 : "=r"(r0), "=r"(r1), "=r"(r2), "=r"(r3) : "r"(addr));
}
__device__ __forceinline__ void mma16816(float* d, const uint32_t* a, const uint32_t* b) {
    asm volatile("mma.sync.aligned.m16n8k16.row.col.f32.f16.f16.f32 "
                 "{%0,%1,%2,%3}, {%4,%5,%6,%7}, {%8,%9}, {%0,%1,%2,%3};"
                 : "+f"(d[0]), "+f"(d[1]), "+f"(d[2]), "+f"(d[3])
                 : "r"(a[0]), "r"(a[1]), "r"(a[2]), "r"(a[3]), "r"(b[0]), "r"(b[1]));
}
// tanh(x) = 1 - 2/(exp(2x)+1), via ex2/rcp approx (rel err ~1e-6)
__device__ __forceinline__ float tanh_fast(float x) {
    float t, r;
    asm("ex2.approx.f32 %0, %1;" : "=f"(t) : "f"(x * 2.8853900817779268f));
    asm("rcp.approx.f32 %0, %1;" : "=f"(r) : "f"(t + 1.0f));
    return fmaf(-2.0f, r, 1.0f);
}

// ---------------- prep: Wk -> fp16 hi/lo ----------------
__global__ void k_prepB(const float* __restrict__ W) {
    int o = blockIdx.x, k = threadIdx.x;
    float x = W[o * (2 * Hh) + Hh + k];
    __half hi = __float2half_rn(x);
    __half lo = __float2half_rn(x - __half2float(hi));
    g_Bh[o * Hh + k] = hi;
    g_Bl[o * Hh + k] = lo;
}

// ---------------- q projection (fp32, exact) ----------------
__global__ void k_qproj(const float* __restrict__ q, const float* __restrict__ W,
                        const float* __restrict__ bvec) {
    __shared__ float sq[Hh];
    int b = blockIdx.x, o = threadIdx.x;
    sq[o] = q[b * Hh + o];
    __syncthreads();
    float s = bvec[o];
    const float* row = W + o * (2 * Hh);
#pragma unroll 8
    for (int h = 0; h < Hh; ++h) s += sq[h] * row[h];
    g_qproj[b * Hh + o] = s;
}

// ---------------- main: fp16-split HMMA GEMM + tanh + dot(v) ----------------
// smem halves-stride 72 (144B rows): conflict-free ldmatrix + stores
#define AST 72
constexpr int AHI_OFF = 0;                       // 128*72*2 = 18432
constexpr int ALO_OFF = 18432;
constexpr int BHI_OFF = 36864;                   // 256*72*2 = 36864
constexpr int BLO_OFF = 73728;
constexpr int QSH_OFF = 110592;                  // 256 f
constexpr int VSH_OFF = 111616;                  // 256 f
constexpr int SCB_OFF = 112640;                  // 128*4 f
constexpr int SMEM_BYTES = 114688;

__global__ void __launch_bounds__(512, 1)
k_scores_mma(const float* __restrict__ key, const float* __restrict__ vvec,
             float* __restrict__ out) {
    extern __shared__ char smem[];
    const uint32_t sbase = smem_u32(smem);

    const int tid  = threadIdx.x;
    const int wid  = tid >> 5;
    const int lane = tid & 31;
    const int wr   = wid >> 2;          // warp row block (32 rows)
    const int wc   = wid & 3;           // warp col block (64 cols)
    const int b    = blockIdx.x >> 6;
    const int s0   = (blockIdx.x & 63) * 128;

    __half* Ah = (__half*)(smem + AHI_OFF);
    __half* Al = (__half*)(smem + ALO_OFF);
    __half* Bh = (__half*)(smem + BHI_OFF);
    __half* Bl = (__half*)(smem + BLO_OFF);
    float* qsh = (float*)(smem + QSH_OFF);
    float* vsh = (float*)(smem + VSH_OFF);
    float* scb = (float*)(smem + SCB_OFF);

    if (tid < 256) {
        qsh[tid] = g_qproj[b * Hh + tid];
        vsh[tid] = vvec[tid];
    }

    const float* kbase = key + ((long long)(b * Ss + s0)) * Hh;

    float acc[2][8][4];
#pragma unroll
    for (int mt = 0; mt < 2; ++mt)
#pragma unroll
        for (int nt = 0; nt < 8; ++nt)
#pragma unroll
            for (int i = 0; i < 4; ++i) acc[mt][nt][i] = 0.f;

    const int quad = lane >> 3;
    const int lr   = lane & 7;

    for (int c = 0; c < 4; ++c) {
        // ---- stage A chunk: 128 rows x 64 K, f32 -> fp16 hi/lo ----
#pragma unroll
        for (int pass = 0; pass < 4; ++pass) {
            int idx = tid + pass * 512;          // 2048 float4s
            int r  = idx >> 4;
            int k4 = (idx & 15) * 4;
            float4 x = __ldg((const float4*)(kbase + (long long)r * Hh + c * 64 + k4));
            __half2 h01 = __floats2half2_rn(x.x, x.y);
            __half2 h23 = __floats2half2_rn(x.z, x.w);
            float2 f01 = __half22float2(h01);
            float2 f23 = __half22float2(h23);
            __half2 l01 = __floats2half2_rn(x.x - f01.x, x.y - f01.y);
            __half2 l23 = __floats2half2_rn(x.z - f23.x, x.w - f23.y);
            *(uint2*)(Ah + r * AST + k4) = make_uint2(*(uint32_t*)&h01, *(uint32_t*)&h23);
            *(uint2*)(Al + r * AST + k4) = make_uint2(*(uint32_t*)&l01, *(uint32_t*)&l23);
        }
        // ---- stage B chunk: 256 rows x 64 K (from prepped global) ----
#pragma unroll
        for (int pass = 0; pass < 4; ++pass) {
            int idx = tid + pass * 512;          // 2048 uint4s per split
            int n   = idx >> 3;
            int k8  = (idx & 7) * 8;
            *(uint4*)(Bh + n * AST + k8) = *(const uint4*)(g_Bh + n * Hh + c * 64 + k8);
            *(uint4*)(Bl + n * AST + k8) = *(const uint4*)(g_Bl + n * Hh + c * 64 + k8);
        }
        __syncthreads();

        // ---- MMA over this chunk: 4 ksteps of 16 ----
#pragma unroll
        for (int ks = 0; ks < 4; ++ks) {
            // A fragments (hi & lo), 2 m-tiles each
            uint32_t ah[2][4], al[2][4];
#pragma unroll
            for (int mt = 0; mt < 2; ++mt) {
                int row = wr * 32 + mt * 16 + (quad & 1) * 8 + lr;
                int col = ks * 16 + (quad >> 1) * 8;
                ldmx4(ah[mt][0], ah[mt][1], ah[mt][2], ah[mt][3],
                      sbase + AHI_OFF + (row * AST + col) * 2);
                ldmx4(al[mt][0], al[mt][1], al[mt][2], al[mt][3],
                      sbase + ALO_OFF + (row * AST + col) * 2);
            }
            uint32_t bf[8][2];
            // B hi fragments: 4 ldmatrix.x4, each covers n16
#pragma unroll
            for (int ng = 0; ng < 4; ++ng) {
                int row = wc * 64 + ng * 16 + (quad >> 1) * 8 + lr;
                int col = ks * 16 + (quad & 1) * 8;
                uint32_t r0, r1, r2, r3;
                ldmx4(r0, r1, r2, r3, sbase + BHI_OFF + (row * AST + col) * 2);
                bf[2 * ng][0] = r0; bf[2 * ng][1] = r1;
                bf[2 * ng + 1][0] = r2; bf[2 * ng + 1][1] = r3;
            }
#pragma unroll
            for (int mt = 0; mt < 2; ++mt)
#pragma unroll
                for (int nt = 0; nt < 8; ++nt) {
                    mma16816(acc[mt][nt], ah[mt], bf[nt]);   // Ahi*Bhi
                    mma16816(acc[mt][nt], al[mt], bf[nt]);   // Alo*Bhi
                }
            // B lo fragments (reuse regs)
#pragma unroll
            for (int ng = 0; ng < 4; ++ng) {
                int row = wc * 64 + ng * 16 + (quad >> 1) * 8 + lr;
                int col = ks * 16 + (quad & 1) * 8;
                uint32_t r0, r1, r2, r3;
                ldmx4(r0, r1, r2, r3, sbase + BLO_OFF + (row * AST + col) * 2);
                bf[2 * ng][0] = r0; bf[2 * ng][1] = r1;
                bf[2 * ng + 1][0] = r2; bf[2 * ng + 1][1] = r3;
            }
#pragma unroll
            for (int mt = 0; mt < 2; ++mt)
#pragma unroll
                for (int nt = 0; nt < 8; ++nt)
                    mma16816(acc[mt][nt], ah[mt], bf[nt]);   // Ahi*Blo
        }
        __syncthreads();
    }

    // ---- epilogue: tanh(d + qproj) * v, reduce over N ----
    const int g  = lane >> 2;
    const int tg = lane & 3;
    float part[4] = {0.f, 0.f, 0.f, 0.f};
#pragma unroll
    for (int mt = 0; mt < 2; ++mt)
#pragma unroll
        for (int nt = 0; nt < 8; ++nt) {
            int col0 = wc * 64 + nt * 8 + tg * 2;
#pragma unroll
            for (int i = 0; i < 4; ++i) {
                int col = col0 + (i & 1);
                float h = tanh_fast(acc[mt][nt][i] + qsh[col]) * vsh[col];
                part[mt * 2 + (i >> 1)] += h;
            }
        }
#pragma unroll
    for (int p = 0; p < 4; ++p) {
        part[p] += __shfl_xor_sync(0xffffffffu, part[p], 1);
        part[p] += __shfl_xor_sync(0xffffffffu, part[p], 2);
    }
    if (tg == 0) {
#pragma unroll
        for (int mt = 0; mt < 2; ++mt)
#pragma unroll
            for (int h = 0; h < 2; ++h) {
                int row = wr * 32 + mt * 16 + h * 8 + g;
                scb[row * 4 + wc] = part[mt * 2 + h];
            }
    }
    __syncthreads();
    if (tid < 128) {
        float s = scb[tid * 4] + scb[tid * 4 + 1] + scb[tid * 4 + 2] + scb[tid * 4 + 3];
        out[ATT_OFF + b * Ss + s0 + tid] = s;
    }
}

// ---------------- softmax stats ----------------
__global__ void k_softmax_stats(const float* __restrict__ out) {
    __shared__ float red[256];
    int b = blockIdx.x, t = threadIdx.x;
    const float* sc = out + ATT_OFF + b * Ss;
    float m = -1e30f;
    for (int i = t; i < Ss; i += 256) m = fmaxf(m, sc[i]);
    red[t] = m; __syncthreads();
    for (int st = 128; st; st >>= 1) {
        if (t < st) red[t] = fmaxf(red[t], red[t + st]);
        __syncthreads();
    }
    float mx = red[0]; __syncthreads();
    float s = 0.f;
    for (int i = t; i < Ss; i += 256) s += expf(sc[i] - mx);
    red[t] = s; __syncthreads();
    for (int st = 128; st; st >>= 1) {
        if (t < st) red[t] += red[t + st];
        __syncthreads();
    }
    if (t == 0) { g_maxv[b] = mx; g_invsum[b] = 1.f / red[0]; }
}

// ---------------- normalize weights + partial context ----------------
#define DCH 512
__global__ void k_context(const float* __restrict__ value, float* __restrict__ out) {
    __shared__ float sw[DCH];
    int b  = blockIdx.x >> 4;
    int ch = blockIdx.x & 15;
    int s0 = ch * DCH;
    int t  = threadIdx.x;
    float mx = g_maxv[b], is = g_invsum[b];
    float* att = out + ATT_OFF + b * Ss;
#pragma unroll
    for (int i = 0; i < 2; ++i) {
        int s = s0 + t + i * 256;
        float w = expf(att[s] - mx) * is;
        att[s] = w;
        sw[t + i * 256] = w;
    }
    __syncthreads();
    const float* vb = value + ((long long)b * Ss + s0) * Hh + t;
    float a0 = 0.f, a1 = 0.f, a2 = 0.f, a3 = 0.f;
#pragma unroll 2
    for (int s = 0; s < DCH; s += 4) {
        a0 += sw[s]     * __ldg(vb + (long long)(s)     * Hh);
        a1 += sw[s + 1] * __ldg(vb + (long long)(s + 1) * Hh);
        a2 += sw[s + 2] * __ldg(vb + (long long)(s + 2) * Hh);
        a3 += sw[s + 3] * __ldg(vb + (long long)(s + 3) * Hh);
    }
    g_ctxpart[(b * 16 + ch) * Hh + t] = (a0 + a1) + (a2 + a3);
}

__global__ void k_reduce_ctx(float* __restrict__ out) {
    int b = blockIdx.x, t = threadIdx.x;
    float s = 0.f;
#pragma unroll
    for (int c = 0; c < 16; ++c) s += g_ctxpart[(b * 16 + c) * Hh + t];
    out[b * Hh + t] = s;
}

// ---------------- launch ----------------
extern "C" void kernel_launch(void* const* d_in, const int* in_sizes, int n_in,
                              void* d_out, int out_size) {
    const float* query  = (const float*)d_in[0];
    const float* key    = (const float*)d_in[1];
    const float* value  = (const float*)d_in[2];
    const float* W_attn = (const float*)d_in[3];
    const float* b_attn = (const float*)d_in[4];
    const float* v      = (const float*)d_in[5];
    float* out = (float*)d_out;

    cudaFuncSetAttribute(k_scores_mma, cudaFuncAttributeMaxDynamicSharedMemorySize, SMEM_BYTES);

    k_prepB<<<256, 256>>>(W_attn);
    k_qproj<<<Bb, Hh>>>(query, W_attn, b_attn);
    k_scores_mma<<<Bb * 64, 512, SMEM_BYTES>>>(key, v, out);
    k_softmax_stats<<<Bb, 256>>>(out);
    k_context<<<Bb * 16, 256>>>(value, out);
    k_reduce_ctx<<<Bb, Hh>>>(out);
}